// round 6
// baseline (speedup 1.0000x reference)
#include <cuda_runtime.h>
#include <cstdint>

#define BB 8
#define SS 1024
#define DD 1024
#define HH 16
#define DHD 64   // head dim

// Scratch (tf32-rounded, octet-permuted cols: slot(w)=2*(w&3)+(w>>2) per 8-col octet):
// g_q [bh][s][64] (pre-scaled by 0.125), g_k [bh][s][64], g_vT [bh][64][s]
__device__ float g_q[BB * HH * SS * DHD];
__device__ float g_k[BB * HH * SS * DHD];
__device__ float g_vT[BB * HH * DHD * SS];

// ---------------- helpers ----------------
__device__ __forceinline__ unsigned long long pack_dup(float x) {
    unsigned long long r;
    asm("mov.b64 %0, {%1, %1};" : "=l"(r) : "f"(x));
    return r;
}
__device__ __forceinline__ void ffma2(unsigned long long& d,
                                      unsigned long long a,
                                      unsigned long long b) {
    asm("fma.rn.f32x2 %0, %1, %2, %0;" : "+l"(d) : "l"(a), "l"(b));
}
__device__ __forceinline__ float2 unpack2(unsigned long long v) {
    float2 f;
    asm("mov.b64 {%0, %1}, %2;" : "=f"(f.x), "=f"(f.y) : "l"(v));
    return f;
}
__device__ __forceinline__ float tf32rn(float x) {
    uint32_t u;
    asm("cvt.rn.tf32.f32 %0, %1;" : "=r"(u) : "f"(x));
    return __uint_as_float(u);
}
__device__ __forceinline__ int sw_vec(int d, int g) {
    return d * 64 + (((g ^ (d >> 2)) & 15) << 2);
}
__device__ __forceinline__ uint32_t smem_to_u32(const void* p) {
    uint32_t a;
    asm("{ .reg .u64 t; cvta.to.shared.u64 t, %1; cvt.u32.u64 %0, t; }"
        : "=r"(a) : "l"(p));
    return a;
}
__device__ __forceinline__ void cp16(uint32_t dst, const void* src) {
    asm volatile("cp.async.cg.shared.global [%0], [%1], 16;"
                 :: "r"(dst), "l"(src) : "memory");
}
#define CP_COMMIT() asm volatile("cp.async.commit_group;" ::: "memory")
#define CP_WAIT_ALL() asm volatile("cp.async.wait_group 0;" ::: "memory")

#define MMA_TF32(c, a, b0, b1) \
    asm volatile("mma.sync.aligned.m16n8k8.row.col.f32.tf32.tf32.f32 " \
        "{%0,%1,%2,%3}, {%4,%5,%6,%7}, {%8,%9}, {%0,%1,%2,%3};" \
        : "+f"((c)[0]), "+f"((c)[1]), "+f"((c)[2]), "+f"((c)[3]) \
        : "r"((a)[0]), "r"((a)[1]), "r"((a)[2]), "r"((a)[3]), \
          "r"(b0), "r"(b1))

// octet-permute a row-chunk float4 using the lane^xorbit partner.
__device__ __forceinline__ float4 perm_shfl(float4 f, int xorbit, bool odd) {
    float4 p;
    p.x = __shfl_xor_sync(0xffffffffu, f.x, xorbit);
    p.y = __shfl_xor_sync(0xffffffffu, f.y, xorbit);
    p.z = __shfl_xor_sync(0xffffffffu, f.z, xorbit);
    p.w = __shfl_xor_sync(0xffffffffu, f.w, xorbit);
    return odd ? make_float4(p.z, f.z, p.w, f.w)
               : make_float4(f.x, p.x, f.y, p.y);
}

// =====================================================================
// Kernel 1: QKV projection (FFMA2 core), permuted tf32 outputs.
// =====================================================================
__global__ __launch_bounds__(256) void qkv_kernel(
    const float* __restrict__ x,
    const float* __restrict__ Wq, const float* __restrict__ bq,
    const float* __restrict__ Wk, const float* __restrict__ bk,
    const float* __restrict__ Wv, const float* __restrict__ bv)
{
    extern __shared__ float sm1[];
    float* Xs  = sm1;
    float* Wqs = sm1 + 4096;
    float* Wks = sm1 + 8192;
    float* Wvs = sm1 + 12288;

    const int tile = blockIdx.x;      // 0..127
    const int h    = blockIdx.y;      // 0..15
    const int tid  = threadIdx.x;
    const int t0   = tile * 64;

#pragma unroll
    for (int k = 0; k < 4; k++) {
        int idx = tid + k * 256;
        int i   = idx >> 4;
        int d4  = (idx & 15) << 2;
        float4 v = *(const float4*)(x + (size_t)(t0 + i) * DD + h * DHD + d4);
        int g = (((i >> 2) ^ (d4 >> 2)) & 15) << 2;
        int o = g + (i & 3);
        Xs[(d4 + 0) * 64 + o] = v.x;
        Xs[(d4 + 1) * 64 + o] = v.y;
        Xs[(d4 + 2) * 64 + o] = v.z;
        Xs[(d4 + 3) * 64 + o] = v.w;
    }
#pragma unroll
    for (int k = 0; k < 4; k++) {
        int idx = tid + k * 256;
        int e   = idx >> 4;
        int d4  = (idx & 15) << 2;
        size_t base = ((size_t)h * DHD + e) * DHD + d4;
        int g = (((e >> 2) ^ (d4 >> 2)) & 15) << 2;
        int o = g + (e & 3);
        float4 a = *(const float4*)(Wq + base);
        Wqs[(d4 + 0) * 64 + o] = a.x; Wqs[(d4 + 1) * 64 + o] = a.y;
        Wqs[(d4 + 2) * 64 + o] = a.z; Wqs[(d4 + 3) * 64 + o] = a.w;
        float4 b = *(const float4*)(Wk + base);
        Wks[(d4 + 0) * 64 + o] = b.x; Wks[(d4 + 1) * 64 + o] = b.y;
        Wks[(d4 + 2) * 64 + o] = b.z; Wks[(d4 + 3) * 64 + o] = b.w;
        float4 c = *(const float4*)(Wv + base);
        Wvs[(d4 + 0) * 64 + o] = c.x; Wvs[(d4 + 1) * 64 + o] = c.y;
        Wvs[(d4 + 2) * 64 + o] = c.z; Wvs[(d4 + 3) * 64 + o] = c.w;
    }
    __syncthreads();

    const int ty = tid >> 4, tx = tid & 15;
    const int r0 = ty * 4, c0 = tx * 4;

    unsigned long long aq[4][2], ak[4][2], av_[4][2];
#pragma unroll
    for (int r = 0; r < 4; r++) {
        aq[r][0] = aq[r][1] = 0ull;
        ak[r][0] = ak[r][1] = 0ull;
        av_[r][0] = av_[r][1] = 0ull;
    }

#pragma unroll 8
    for (int d = 0; d < 64; d++) {
        float4 a4 = *(const float4*)&Xs[sw_vec(d, ty)];
        unsigned long long d0 = pack_dup(a4.x), d1 = pack_dup(a4.y),
                           d2 = pack_dup(a4.z), d3 = pack_dup(a4.w);
        ulonglong2 q2 = *(const ulonglong2*)&Wqs[sw_vec(d, tx)];
        ulonglong2 k2 = *(const ulonglong2*)&Wks[sw_vec(d, tx)];
        ulonglong2 v2 = *(const ulonglong2*)&Wvs[sw_vec(d, tx)];
        ffma2(aq[0][0], d0, q2.x); ffma2(aq[0][1], d0, q2.y);
        ffma2(aq[1][0], d1, q2.x); ffma2(aq[1][1], d1, q2.y);
        ffma2(aq[2][0], d2, q2.x); ffma2(aq[2][1], d2, q2.y);
        ffma2(aq[3][0], d3, q2.x); ffma2(aq[3][1], d3, q2.y);
        ffma2(ak[0][0], d0, k2.x); ffma2(ak[0][1], d0, k2.y);
        ffma2(ak[1][0], d1, k2.x); ffma2(ak[1][1], d1, k2.y);
        ffma2(ak[2][0], d2, k2.x); ffma2(ak[2][1], d2, k2.y);
        ffma2(ak[3][0], d3, k2.x); ffma2(ak[3][1], d3, k2.y);
        ffma2(av_[0][0], d0, v2.x); ffma2(av_[0][1], d0, v2.y);
        ffma2(av_[1][0], d1, v2.x); ffma2(av_[1][1], d1, v2.y);
        ffma2(av_[2][0], d2, v2.x); ffma2(av_[2][1], d2, v2.y);
        ffma2(av_[3][0], d3, v2.x); ffma2(av_[3][1], d3, v2.y);
    }

    float4 bq4 = *(const float4*)(bq + h * DHD + c0);
    float4 bk4 = *(const float4*)(bk + h * DHD + c0);
    float4 bv4 = *(const float4*)(bv + h * DHD + c0);

    const int bb = t0 >> 10;
    const int s0 = (t0 & 1023) + r0;
    const int bh = bb * HH + h;
    const bool oddx = (tx & 1);
    const bool oddy = (ty & 1);

    float vv[4][4];
#pragma unroll
    for (int r = 0; r < 4; r++) {
        size_t o = ((size_t)bh * SS + s0 + r) * DHD + c0;
        float2 u0, u1;
        u0 = unpack2(aq[r][0]); u1 = unpack2(aq[r][1]);
        float4 fq = make_float4(
            tf32rn((u0.x + bq4.x) * 0.125f), tf32rn((u0.y + bq4.y) * 0.125f),
            tf32rn((u1.x + bq4.z) * 0.125f), tf32rn((u1.y + bq4.w) * 0.125f));
        *(float4*)&g_q[o] = perm_shfl(fq, 1, oddx);
        u0 = unpack2(ak[r][0]); u1 = unpack2(ak[r][1]);
        float4 fk = make_float4(
            tf32rn(u0.x + bk4.x), tf32rn(u0.y + bk4.y),
            tf32rn(u1.x + bk4.z), tf32rn(u1.y + bk4.w));
        *(float4*)&g_k[o] = perm_shfl(fk, 1, oddx);
        u0 = unpack2(av_[r][0]); u1 = unpack2(av_[r][1]);
        vv[r][0] = tf32rn(u0.x + bv4.x); vv[r][1] = tf32rn(u0.y + bv4.y);
        vv[r][2] = tf32rn(u1.x + bv4.z); vv[r][3] = tf32rn(u1.y + bv4.w);
    }
#pragma unroll
    for (int j = 0; j < 4; j++) {
        float4 ft = make_float4(vv[0][j], vv[1][j], vv[2][j], vv[3][j]);
        size_t o = ((size_t)bh * DHD + c0 + j) * SS + s0;
        *(float4*)&g_vT[o] = perm_shfl(ft, 16, oddy);
    }
}

// =====================================================================
// Kernel 2: tf32 mma.sync flash attention, 128 threads (4 warps, 2m x 2n),
// 64 q-rows per CTA, KV tile 64, cp.async double-buffered.
// P OVERLAYS the current K buffer (K dead after S-MMA) -> smem 78.3KB,
// guaranteeing 2 CTAs/SM. 3 syncs/kt. No-max softmax.
// =====================================================================
#define SPW 76
#define K0F 0
#define K1F 4864          // 64*76
#define V0F 9728
#define V1F 14592
#define LRF 19456         // 128 floats
#define ATTN_SMEM ((19456 + 128) * 4)   // 78336 B

__global__ void __launch_bounds__(128, 2) attn_kernel(float* __restrict__ out)
{
    extern __shared__ float smf[];
    const uint32_t smb = smem_to_u32(smf);
    const int tid  = threadIdx.x;
    const int wid  = tid >> 5;
    const int lane = tid & 31;
    const int g    = lane >> 2;
    const int c    = lane & 3;
    const int wm   = wid >> 1;      // 0..1 -> rows wm*32..
    const int wn   = wid & 1;       // 0..1 -> cols wn*32..

    const int qt = blockIdx.x;      // 0..15
    const int bh = blockIdx.y;      // 0..127
    const int b  = bh >> 4, h = bh & 15;
    const int m0 = qt * 64;

    const float* qbase = g_q + (size_t)bh * SS * DHD;
    const float* kbase = g_k + (size_t)bh * SS * DHD;
    const float* vTb   = g_vT + (size_t)bh * DHD * SS;

    float* lred = smf + LRF;

    const int prow = tid >> 4;       // 0..7
    const int pch  = tid & 15;       // 16B chunk

    // ---- prologue: async-load KV tile 0 into buffer 0 ----
#pragma unroll
    for (int p = 0; p < 8; p++) {
        int r = prow + p * 8;
        cp16(smb + (K0F + r * SPW + pch * 4) * 4,
             kbase + (size_t)r * DHD + pch * 4);
        cp16(smb + (V0F + r * SPW + pch * 4) * 4,
             vTb + (size_t)r * SS + pch * 4);
    }
    CP_COMMIT();

    // ---- stage Q (permuted) into K1 buffer, stride 76 ----
    {
        float* Qst = smf + K1F;
#pragma unroll
        for (int it = 0; it < 8; it++) {
            int idx = tid + it * 128;
            int row = idx >> 4;
            int ch  = idx & 15;
            *(float4*)&Qst[row * SPW + ch * 4] =
                *(const float4*)(qbase + (size_t)(m0 + row) * DHD + ch * 4);
        }
    }
    __syncthreads();

    uint32_t qa[2][8][4];
    {
        const float* Qst = smf + K1F;
#pragma unroll
        for (int m = 0; m < 2; m++) {
            int r = wm * 32 + m * 16 + g;
#pragma unroll
            for (int s = 0; s < 8; s++) {
                float2 lo = *(const float2*)&Qst[r * SPW + s * 8 + 2 * c];
                float2 hi = *(const float2*)&Qst[(r + 8) * SPW + s * 8 + 2 * c];
                qa[m][s][0] = __float_as_uint(lo.x);
                qa[m][s][1] = __float_as_uint(hi.x);
                qa[m][s][2] = __float_as_uint(lo.y);
                qa[m][s][3] = __float_as_uint(hi.y);
            }
        }
    }

    float oacc[2][4][4];
#pragma unroll
    for (int m = 0; m < 2; m++)
#pragma unroll
        for (int t = 0; t < 4; t++)
#pragma unroll
            for (int q = 0; q < 4; q++) oacc[m][t][q] = 0.f;
    float lacc[2][2] = {{0.f, 0.f}, {0.f, 0.f}};

    const int sl0 = ((c & 1) << 2) | (c >> 1);   // slot(2c); slot(2c+1)=sl0+2

    for (int kt = 0; kt < 16; kt++) {
        CP_WAIT_ALL();
        __syncthreads();  // tile kt K/V visible; Q frags loaded (iter 0);
                          // prev-iter P/V reads done -> buffers reusable

        // prefetch kt+1 into the other buffer pair
        if (kt < 15) {
            int kb = (kt & 1) ? K0F : K1F;
            int vb = (kt & 1) ? V0F : V1F;
#pragma unroll
            for (int p = 0; p < 8; p++) {
                int r = prow + p * 8;
                cp16(smb + (kb + r * SPW + pch * 4) * 4,
                     kbase + (size_t)((kt + 1) * 64 + r) * DHD + pch * 4);
                cp16(smb + (vb + r * SPW + pch * 4) * 4,
                     vTb + (size_t)r * SS + (kt + 1) * 64 + pch * 4);
            }
            CP_COMMIT();
        }

        // ---- S = Q K^T ----
        float* Kb = smf + ((kt & 1) ? K1F : K0F);   // also P home this iter
        float sacc[2][4][4];
#pragma unroll
        for (int m = 0; m < 2; m++)
#pragma unroll
            for (int t = 0; t < 4; t++)
#pragma unroll
                for (int q = 0; q < 4; q++) sacc[m][t][q] = 0.f;
#pragma unroll
        for (int t = 0; t < 4; t++) {
            const float* bp = Kb + (wn * 32 + t * 8 + g) * SPW + 2 * c;
#pragma unroll
            for (int s = 0; s < 8; s++) {
                float2 b2 = *(const float2*)(bp + s * 8);
                uint32_t b0 = __float_as_uint(b2.x), b1 = __float_as_uint(b2.y);
                MMA_TF32(sacc[0][t], qa[0][s], b0, b1);
                MMA_TF32(sacc[1][t], qa[1][s], b0, b1);
            }
        }
        __syncthreads();  // all warps done reading K tile -> P may overwrite

        // ---- softmax (no max) + permuted P store into K buffer ----
#pragma unroll
        for (int m = 0; m < 2; m++) {
            int r = wm * 32 + m * 16 + g;
            float* p0 = Kb + r * SPW + wn * 32;
            float* p1 = Kb + (r + 8) * SPW + wn * 32;
#pragma unroll
            for (int t = 0; t < 4; t++) {
                float e0 = tf32rn(__expf(sacc[m][t][0]));
                float e1 = tf32rn(__expf(sacc[m][t][1]));
                float e2 = tf32rn(__expf(sacc[m][t][2]));
                float e3 = tf32rn(__expf(sacc[m][t][3]));
                lacc[m][0] += e0 + e1;
                lacc[m][1] += e2 + e3;
                p0[t * 8 + sl0]     = e0;
                p0[t * 8 + sl0 + 2] = e1;
                p1[t * 8 + sl0]     = e2;
                p1[t * 8 + sl0 + 2] = e3;
            }
        }
        __syncthreads();  // P visible

        // ---- O += P V ----
        const float* Vb = smf + ((kt & 1) ? V1F : V0F);
#pragma unroll
        for (int s = 0; s < 8; s++) {
            uint32_t pa[2][4];
#pragma unroll
            for (int m = 0; m < 2; m++) {
                int r = wm * 32 + m * 16 + g;
                float2 a0 = *(const float2*)(Kb + r * SPW + s * 8 + 2 * c);
                float2 a1 = *(const float2*)(Kb + (r + 8) * SPW + s * 8 + 2 * c);
                pa[m][0] = __float_as_uint(a0.x);
                pa[m][1] = __float_as_uint(a1.x);
                pa[m][2] = __float_as_uint(a0.y);
                pa[m][3] = __float_as_uint(a1.y);
            }
#pragma unroll
            for (int t = 0; t < 4; t++) {
                float2 b2 = *(const float2*)(Vb + (wn * 32 + t * 8 + g) * SPW + s * 8 + 2 * c);
                uint32_t b0 = __float_as_uint(b2.x), b1 = __float_as_uint(b2.y);
                MMA_TF32(oacc[0][t], pa[0], b0, b1);
                MMA_TF32(oacc[1][t], pa[1], b0, b1);
            }
        }
    }

    // ---- epilogue: reduce l, normalize, store ----
#pragma unroll
    for (int m = 0; m < 2; m++)
#pragma unroll
        for (int hh = 0; hh < 2; hh++) {
            lacc[m][hh] += __shfl_xor_sync(0xffffffffu, lacc[m][hh], 1);
            lacc[m][hh] += __shfl_xor_sync(0xffffffffu, lacc[m][hh], 2);
        }
    if (c == 0) {
#pragma unroll
        for (int m = 0; m < 2; m++) {
            int r = wm * 32 + m * 16 + g;
            lred[r * 2 + wn]       = lacc[m][0];
            lred[(r + 8) * 2 + wn] = lacc[m][1];
        }
    }
    __syncthreads();

#pragma unroll
    for (int m = 0; m < 2; m++) {
        int r = wm * 32 + m * 16 + g;
        float inv0 = 1.f / (lred[r * 2] + lred[r * 2 + 1]);
        float inv1 = 1.f / (lred[(r + 8) * 2] + lred[(r + 8) * 2 + 1]);
        size_t o0 = (((size_t)b * SS + m0 + r) * HH + h) * DHD;
        size_t o1 = (((size_t)b * SS + m0 + r + 8) * HH + h) * DHD;
#pragma unroll
        for (int t = 0; t < 4; t++) {
            int col = wn * 32 + t * 8 + 2 * c;
            *(float2*)&out[o0 + col] =
                make_float2(oacc[m][t][0] * inv0, oacc[m][t][1] * inv0);
            *(float2*)&out[o1 + col] =
                make_float2(oacc[m][t][2] * inv1, oacc[m][t][3] * inv1);
        }
    }
}

// =====================================================================
extern "C" void kernel_launch(void* const* d_in, const int* in_sizes, int n_in,
                              void* d_out, int out_size)
{
    const float* x  = (const float*)d_in[0];
    const float* Wq = (const float*)d_in[1];
    const float* bq = (const float*)d_in[2];
    const float* Wk = (const float*)d_in[3];
    const float* bk = (const float*)d_in[4];
    const float* Wv = (const float*)d_in[5];
    const float* bv = (const float*)d_in[6];
    float* out = (float*)d_out;

    static bool attr_set = false;
    if (!attr_set) {
        cudaFuncSetAttribute(qkv_kernel,
                             cudaFuncAttributeMaxDynamicSharedMemorySize, 65536);
        cudaFuncSetAttribute(attn_kernel,
                             cudaFuncAttributeMaxDynamicSharedMemorySize, ATTN_SMEM);
        attr_set = true;
    }

    qkv_kernel<<<dim3(128, 16), 256, 65536>>>(x, Wq, bq, Wk, bk, Wv, bv);
    attn_kernel<<<dim3(16, 128), 128, ATTN_SMEM>>>(out);
}

// round 8
// speedup vs baseline: 1.1679x; 1.1679x over previous
#include <cuda_runtime.h>
#include <cstdint>

#define BB 8
#define SS 1024
#define DD 1024
#define HH 16
#define DHD 64   // head dim

// Scratch (tf32-rounded, octet-permuted cols: slot(w)=2*(w&3)+(w>>2) per 8-col octet):
// g_q [bh][s][64] (pre-scaled by 0.125), g_k [bh][s][64], g_vT [bh][64][s]
__device__ float g_q[BB * HH * SS * DHD];
__device__ float g_k[BB * HH * SS * DHD];
__device__ float g_vT[BB * HH * DHD * SS];

// ---------------- helpers ----------------
__device__ __forceinline__ unsigned long long pack_dup(float x) {
    unsigned long long r;
    asm("mov.b64 %0, {%1, %1};" : "=l"(r) : "f"(x));
    return r;
}
__device__ __forceinline__ void ffma2(unsigned long long& d,
                                      unsigned long long a,
                                      unsigned long long b) {
    asm("fma.rn.f32x2 %0, %1, %2, %0;" : "+l"(d) : "l"(a), "l"(b));
}
__device__ __forceinline__ float2 unpack2(unsigned long long v) {
    float2 f;
    asm("mov.b64 {%0, %1}, %2;" : "=f"(f.x), "=f"(f.y) : "l"(v));
    return f;
}
__device__ __forceinline__ float tf32rn(float x) {
    uint32_t u;
    asm("cvt.rn.tf32.f32 %0, %1;" : "=r"(u) : "f"(x));
    return __uint_as_float(u);
}
__device__ __forceinline__ int sw_vec(int d, int g) {
    return d * 64 + (((g ^ (d >> 2)) & 15) << 2);
}
__device__ __forceinline__ uint32_t smem_to_u32(const void* p) {
    uint32_t a;
    asm("{ .reg .u64 t; cvta.to.shared.u64 t, %1; cvt.u32.u64 %0, t; }"
        : "=r"(a) : "l"(p));
    return a;
}
__device__ __forceinline__ void cp16(uint32_t dst, const void* src) {
    asm volatile("cp.async.cg.shared.global [%0], [%1], 16;"
                 :: "r"(dst), "l"(src) : "memory");
}
#define CP_COMMIT() asm volatile("cp.async.commit_group;" ::: "memory")
#define CP_WAIT_ALL() asm volatile("cp.async.wait_group 0;" ::: "memory")

#define MMA_TF32(c, a, b0, b1) \
    asm volatile("mma.sync.aligned.m16n8k8.row.col.f32.tf32.tf32.f32 " \
        "{%0,%1,%2,%3}, {%4,%5,%6,%7}, {%8,%9}, {%0,%1,%2,%3};" \
        : "+f"((c)[0]), "+f"((c)[1]), "+f"((c)[2]), "+f"((c)[3]) \
        : "r"((a)[0]), "r"((a)[1]), "r"((a)[2]), "r"((a)[3]), \
          "r"(b0), "r"(b1))

// octet-permute a row-chunk float4 using the lane^xorbit partner.
__device__ __forceinline__ float4 perm_shfl(float4 f, int xorbit, bool odd) {
    float4 p;
    p.x = __shfl_xor_sync(0xffffffffu, f.x, xorbit);
    p.y = __shfl_xor_sync(0xffffffffu, f.y, xorbit);
    p.z = __shfl_xor_sync(0xffffffffu, f.z, xorbit);
    p.w = __shfl_xor_sync(0xffffffffu, f.w, xorbit);
    return odd ? make_float4(p.z, f.z, p.w, f.w)
               : make_float4(f.x, p.x, f.y, p.y);
}

// =====================================================================
// Kernel 1: QKV projection (FFMA2 core), permuted tf32 outputs.
// =====================================================================
__global__ __launch_bounds__(256) void qkv_kernel(
    const float* __restrict__ x,
    const float* __restrict__ Wq, const float* __restrict__ bq,
    const float* __restrict__ Wk, const float* __restrict__ bk,
    const float* __restrict__ Wv, const float* __restrict__ bv)
{
    extern __shared__ float sm1[];
    float* Xs  = sm1;
    float* Wqs = sm1 + 4096;
    float* Wks = sm1 + 8192;
    float* Wvs = sm1 + 12288;

    const int tile = blockIdx.x;      // 0..127
    const int h    = blockIdx.y;      // 0..15
    const int tid  = threadIdx.x;
    const int t0   = tile * 64;

#pragma unroll
    for (int k = 0; k < 4; k++) {
        int idx = tid + k * 256;
        int i   = idx >> 4;
        int d4  = (idx & 15) << 2;
        float4 v = *(const float4*)(x + (size_t)(t0 + i) * DD + h * DHD + d4);
        int g = (((i >> 2) ^ (d4 >> 2)) & 15) << 2;
        int o = g + (i & 3);
        Xs[(d4 + 0) * 64 + o] = v.x;
        Xs[(d4 + 1) * 64 + o] = v.y;
        Xs[(d4 + 2) * 64 + o] = v.z;
        Xs[(d4 + 3) * 64 + o] = v.w;
    }
#pragma unroll
    for (int k = 0; k < 4; k++) {
        int idx = tid + k * 256;
        int e   = idx >> 4;
        int d4  = (idx & 15) << 2;
        size_t base = ((size_t)h * DHD + e) * DHD + d4;
        int g = (((e >> 2) ^ (d4 >> 2)) & 15) << 2;
        int o = g + (e & 3);
        float4 a = *(const float4*)(Wq + base);
        Wqs[(d4 + 0) * 64 + o] = a.x; Wqs[(d4 + 1) * 64 + o] = a.y;
        Wqs[(d4 + 2) * 64 + o] = a.z; Wqs[(d4 + 3) * 64 + o] = a.w;
        float4 b = *(const float4*)(Wk + base);
        Wks[(d4 + 0) * 64 + o] = b.x; Wks[(d4 + 1) * 64 + o] = b.y;
        Wks[(d4 + 2) * 64 + o] = b.z; Wks[(d4 + 3) * 64 + o] = b.w;
        float4 c = *(const float4*)(Wv + base);
        Wvs[(d4 + 0) * 64 + o] = c.x; Wvs[(d4 + 1) * 64 + o] = c.y;
        Wvs[(d4 + 2) * 64 + o] = c.z; Wvs[(d4 + 3) * 64 + o] = c.w;
    }
    __syncthreads();

    const int ty = tid >> 4, tx = tid & 15;
    const int r0 = ty * 4, c0 = tx * 4;

    unsigned long long aq[4][2], ak[4][2], av_[4][2];
#pragma unroll
    for (int r = 0; r < 4; r++) {
        aq[r][0] = aq[r][1] = 0ull;
        ak[r][0] = ak[r][1] = 0ull;
        av_[r][0] = av_[r][1] = 0ull;
    }

#pragma unroll 8
    for (int d = 0; d < 64; d++) {
        float4 a4 = *(const float4*)&Xs[sw_vec(d, ty)];
        unsigned long long d0 = pack_dup(a4.x), d1 = pack_dup(a4.y),
                           d2 = pack_dup(a4.z), d3 = pack_dup(a4.w);
        ulonglong2 q2 = *(const ulonglong2*)&Wqs[sw_vec(d, tx)];
        ulonglong2 k2 = *(const ulonglong2*)&Wks[sw_vec(d, tx)];
        ulonglong2 v2 = *(const ulonglong2*)&Wvs[sw_vec(d, tx)];
        ffma2(aq[0][0], d0, q2.x); ffma2(aq[0][1], d0, q2.y);
        ffma2(aq[1][0], d1, q2.x); ffma2(aq[1][1], d1, q2.y);
        ffma2(aq[2][0], d2, q2.x); ffma2(aq[2][1], d2, q2.y);
        ffma2(aq[3][0], d3, q2.x); ffma2(aq[3][1], d3, q2.y);
        ffma2(ak[0][0], d0, k2.x); ffma2(ak[0][1], d0, k2.y);
        ffma2(ak[1][0], d1, k2.x); ffma2(ak[1][1], d1, k2.y);
        ffma2(ak[2][0], d2, k2.x); ffma2(ak[2][1], d2, k2.y);
        ffma2(ak[3][0], d3, k2.x); ffma2(ak[3][1], d3, k2.y);
        ffma2(av_[0][0], d0, v2.x); ffma2(av_[0][1], d0, v2.y);
        ffma2(av_[1][0], d1, v2.x); ffma2(av_[1][1], d1, v2.y);
        ffma2(av_[2][0], d2, v2.x); ffma2(av_[2][1], d2, v2.y);
        ffma2(av_[3][0], d3, v2.x); ffma2(av_[3][1], d3, v2.y);
    }

    float4 bq4 = *(const float4*)(bq + h * DHD + c0);
    float4 bk4 = *(const float4*)(bk + h * DHD + c0);
    float4 bv4 = *(const float4*)(bv + h * DHD + c0);

    const int bb = t0 >> 10;
    const int s0 = (t0 & 1023) + r0;
    const int bh = bb * HH + h;
    const bool oddx = (tx & 1);
    const bool oddy = (ty & 1);

    float vv[4][4];
#pragma unroll
    for (int r = 0; r < 4; r++) {
        size_t o = ((size_t)bh * SS + s0 + r) * DHD + c0;
        float2 u0, u1;
        u0 = unpack2(aq[r][0]); u1 = unpack2(aq[r][1]);
        float4 fq = make_float4(
            tf32rn((u0.x + bq4.x) * 0.125f), tf32rn((u0.y + bq4.y) * 0.125f),
            tf32rn((u1.x + bq4.z) * 0.125f), tf32rn((u1.y + bq4.w) * 0.125f));
        *(float4*)&g_q[o] = perm_shfl(fq, 1, oddx);
        u0 = unpack2(ak[r][0]); u1 = unpack2(ak[r][1]);
        float4 fk = make_float4(
            tf32rn(u0.x + bk4.x), tf32rn(u0.y + bk4.y),
            tf32rn(u1.x + bk4.z), tf32rn(u1.y + bk4.w));
        *(float4*)&g_k[o] = perm_shfl(fk, 1, oddx);
        u0 = unpack2(av_[r][0]); u1 = unpack2(av_[r][1]);
        vv[r][0] = tf32rn(u0.x + bv4.x); vv[r][1] = tf32rn(u0.y + bv4.y);
        vv[r][2] = tf32rn(u1.x + bv4.z); vv[r][3] = tf32rn(u1.y + bv4.w);
    }
#pragma unroll
    for (int j = 0; j < 4; j++) {
        float4 ft = make_float4(vv[0][j], vv[1][j], vv[2][j], vv[3][j]);
        size_t o = ((size_t)bh * DHD + c0 + j) * SS + s0;
        *(float4*)&g_vT[o] = perm_shfl(ft, 16, oddy);
    }
}

// =====================================================================
// Kernel 2: tf32 mma.sync flash attention, 128 threads (4 warps, 2m x 2n),
// 64 q-rows per CTA, KV tile 64, cp.async double-buffered, P overlays
// the dead K buffer. SPW=72 -> LDS.64 fragment loads are pair-bank
// conflict-free (pair-stride 36 == 4 mod 16 -> bank 4g+c, a permutation
// per 16-lane phase). smem 74,240B -> up to 3 CTAs/SM with regs<=170.
// =====================================================================
#define SPW 72
#define K0F 0
#define K1F 4608          // 64*72
#define V0F 9216
#define V1F 13824
#define LRF 18432         // 128 floats
#define ATTN_SMEM ((18432 + 128) * 4)   // 74240 B

__global__ void __launch_bounds__(128, 3) attn_kernel(float* __restrict__ out)
{
    extern __shared__ float smf[];
    const uint32_t smb = smem_to_u32(smf);
    const int tid  = threadIdx.x;
    const int wid  = tid >> 5;
    const int lane = tid & 31;
    const int g    = lane >> 2;
    const int c    = lane & 3;
    const int wm   = wid >> 1;      // 0..1 -> rows wm*32..
    const int wn   = wid & 1;       // 0..1 -> cols wn*32..

    const int qt = blockIdx.x;      // 0..15
    const int bh = blockIdx.y;      // 0..127
    const int b  = bh >> 4, h = bh & 15;
    const int m0 = qt * 64;

    const float* qbase = g_q + (size_t)bh * SS * DHD;
    const float* kbase = g_k + (size_t)bh * SS * DHD;
    const float* vTb   = g_vT + (size_t)bh * DHD * SS;

    float* lred = smf + LRF;

    const int prow = tid >> 4;       // 0..7
    const int pch  = tid & 15;       // 16B chunk

    // ---- prologue: async-load KV tile 0 into buffer 0 ----
#pragma unroll
    for (int p = 0; p < 8; p++) {
        int r = prow + p * 8;
        cp16(smb + (K0F + r * SPW + pch * 4) * 4,
             kbase + (size_t)r * DHD + pch * 4);
        cp16(smb + (V0F + r * SPW + pch * 4) * 4,
             vTb + (size_t)r * SS + pch * 4);
    }
    CP_COMMIT();

    // ---- stage Q (permuted) into K1 buffer, stride SPW ----
    {
        float* Qst = smf + K1F;
#pragma unroll
        for (int it = 0; it < 8; it++) {
            int idx = tid + it * 128;
            int row = idx >> 4;
            int ch  = idx & 15;
            *(float4*)&Qst[row * SPW + ch * 4] =
                *(const float4*)(qbase + (size_t)(m0 + row) * DHD + ch * 4);
        }
    }
    __syncthreads();

    uint32_t qa[2][8][4];
    {
        const float* Qst = smf + K1F;
#pragma unroll
        for (int m = 0; m < 2; m++) {
            int r = wm * 32 + m * 16 + g;
#pragma unroll
            for (int s = 0; s < 8; s++) {
                float2 lo = *(const float2*)&Qst[r * SPW + s * 8 + 2 * c];
                float2 hi = *(const float2*)&Qst[(r + 8) * SPW + s * 8 + 2 * c];
                qa[m][s][0] = __float_as_uint(lo.x);
                qa[m][s][1] = __float_as_uint(hi.x);
                qa[m][s][2] = __float_as_uint(lo.y);
                qa[m][s][3] = __float_as_uint(hi.y);
            }
        }
    }

    float oacc[2][4][4];
#pragma unroll
    for (int m = 0; m < 2; m++)
#pragma unroll
        for (int t = 0; t < 4; t++)
#pragma unroll
            for (int q = 0; q < 4; q++) oacc[m][t][q] = 0.f;
    float lacc[2][2] = {{0.f, 0.f}, {0.f, 0.f}};

    const int sl0 = ((c & 1) << 2) | (c >> 1);   // slot(2c); slot(2c+1)=sl0+2

    for (int kt = 0; kt < 16; kt++) {
        CP_WAIT_ALL();
        __syncthreads();  // tile kt K/V visible; Q frags loaded (iter 0);
                          // prev-iter P/V reads done -> buffers reusable

        // prefetch kt+1 into the other buffer pair
        if (kt < 15) {
            int kb = (kt & 1) ? K0F : K1F;
            int vb = (kt & 1) ? V0F : V1F;
#pragma unroll
            for (int p = 0; p < 8; p++) {
                int r = prow + p * 8;
                cp16(smb + (kb + r * SPW + pch * 4) * 4,
                     kbase + (size_t)((kt + 1) * 64 + r) * DHD + pch * 4);
                cp16(smb + (vb + r * SPW + pch * 4) * 4,
                     vTb + (size_t)r * SS + (kt + 1) * 64 + pch * 4);
            }
            CP_COMMIT();
        }

        // ---- S = Q K^T ----
        float* Kb = smf + ((kt & 1) ? K1F : K0F);   // also P home this iter
        float sacc[2][4][4];
#pragma unroll
        for (int m = 0; m < 2; m++)
#pragma unroll
            for (int t = 0; t < 4; t++)
#pragma unroll
                for (int q = 0; q < 4; q++) sacc[m][t][q] = 0.f;
#pragma unroll
        for (int t = 0; t < 4; t++) {
            const float* bp = Kb + (wn * 32 + t * 8 + g) * SPW + 2 * c;
#pragma unroll
            for (int s = 0; s < 8; s++) {
                float2 b2 = *(const float2*)(bp + s * 8);
                uint32_t b0 = __float_as_uint(b2.x), b1 = __float_as_uint(b2.y);
                MMA_TF32(sacc[0][t], qa[0][s], b0, b1);
                MMA_TF32(sacc[1][t], qa[1][s], b0, b1);
            }
        }
        __syncthreads();  // all warps done reading K tile -> P may overwrite

        // ---- softmax (no max) + permuted P store into K buffer ----
#pragma unroll
        for (int m = 0; m < 2; m++) {
            int r = wm * 32 + m * 16 + g;
            float* p0 = Kb + r * SPW + wn * 32;
            float* p1 = Kb + (r + 8) * SPW + wn * 32;
#pragma unroll
            for (int t = 0; t < 4; t++) {
                float e0 = tf32rn(__expf(sacc[m][t][0]));
                float e1 = tf32rn(__expf(sacc[m][t][1]));
                float e2 = tf32rn(__expf(sacc[m][t][2]));
                float e3 = tf32rn(__expf(sacc[m][t][3]));
                lacc[m][0] += e0 + e1;
                lacc[m][1] += e2 + e3;
                p0[t * 8 + sl0]     = e0;
                p0[t * 8 + sl0 + 2] = e1;
                p1[t * 8 + sl0]     = e2;
                p1[t * 8 + sl0 + 2] = e3;
            }
        }
        __syncthreads();  // P visible

        // ---- O += P V ----
        const float* Vb = smf + ((kt & 1) ? V1F : V0F);
#pragma unroll
        for (int s = 0; s < 8; s++) {
            uint32_t pa[2][4];
#pragma unroll
            for (int m = 0; m < 2; m++) {
                int r = wm * 32 + m * 16 + g;
                float2 a0 = *(const float2*)(Kb + r * SPW + s * 8 + 2 * c);
                float2 a1 = *(const float2*)(Kb + (r + 8) * SPW + s * 8 + 2 * c);
                pa[m][0] = __float_as_uint(a0.x);
                pa[m][1] = __float_as_uint(a1.x);
                pa[m][2] = __float_as_uint(a0.y);
                pa[m][3] = __float_as_uint(a1.y);
            }
#pragma unroll
            for (int t = 0; t < 4; t++) {
                float2 b2 = *(const float2*)(Vb + (wn * 32 + t * 8 + g) * SPW + s * 8 + 2 * c);
                uint32_t b0 = __float_as_uint(b2.x), b1 = __float_as_uint(b2.y);
                MMA_TF32(oacc[0][t], pa[0], b0, b1);
                MMA_TF32(oacc[1][t], pa[1], b0, b1);
            }
        }
    }

    // ---- epilogue: reduce l, normalize, store ----
#pragma unroll
    for (int m = 0; m < 2; m++)
#pragma unroll
        for (int hh = 0; hh < 2; hh++) {
            lacc[m][hh] += __shfl_xor_sync(0xffffffffu, lacc[m][hh], 1);
            lacc[m][hh] += __shfl_xor_sync(0xffffffffu, lacc[m][hh], 2);
        }
    if (c == 0) {
#pragma unroll
        for (int m = 0; m < 2; m++) {
            int r = wm * 32 + m * 16 + g;
            lred[r * 2 + wn]       = lacc[m][0];
            lred[(r + 8) * 2 + wn] = lacc[m][1];
        }
    }
    __syncthreads();

#pragma unroll
    for (int m = 0; m < 2; m++) {
        int r = wm * 32 + m * 16 + g;
        float inv0 = 1.f / (lred[r * 2] + lred[r * 2 + 1]);
        float inv1 = 1.f / (lred[(r + 8) * 2] + lred[(r + 8) * 2 + 1]);
        size_t o0 = (((size_t)b * SS + m0 + r) * HH + h) * DHD;
        size_t o1 = (((size_t)b * SS + m0 + r + 8) * HH + h) * DHD;
#pragma unroll
        for (int t = 0; t < 4; t++) {
            int col = wn * 32 + t * 8 + 2 * c;
            *(float2*)&out[o0 + col] =
                make_float2(oacc[m][t][0] * inv0, oacc[m][t][1] * inv0);
            *(float2*)&out[o1 + col] =
                make_float2(oacc[m][t][2] * inv1, oacc[m][t][3] * inv1);
        }
    }
}

// =====================================================================
extern "C" void kernel_launch(void* const* d_in, const int* in_sizes, int n_in,
                              void* d_out, int out_size)
{
    const float* x  = (const float*)d_in[0];
    const float* Wq = (const float*)d_in[1];
    const float* bq = (const float*)d_in[2];
    const float* Wk = (const float*)d_in[3];
    const float* bk = (const float*)d_in[4];
    const float* Wv = (const float*)d_in[5];
    const float* bv = (const float*)d_in[6];
    float* out = (float*)d_out;

    static bool attr_set = false;
    if (!attr_set) {
        cudaFuncSetAttribute(qkv_kernel,
                             cudaFuncAttributeMaxDynamicSharedMemorySize, 65536);
        cudaFuncSetAttribute(attn_kernel,
                             cudaFuncAttributeMaxDynamicSharedMemorySize, ATTN_SMEM);
        attr_set = true;
    }

    qkv_kernel<<<dim3(128, 16), 256, 65536>>>(x, Wq, bq, Wk, bk, Wv, bv);
    attn_kernel<<<dim3(16, 128), 128, ATTN_SMEM>>>(out);
}

// round 9
// speedup vs baseline: 1.3162x; 1.1270x over previous
#include <cuda_runtime.h>
#include <cstdint>

#define BB 8
#define SS 1024
#define DD 1024
#define HH 16
#define DHD 64   // head dim

// Scratch (tf32-rounded, octet-permuted cols: slot(w)=2*(w&3)+(w>>2) per 8-col octet):
// g_q [bh][s][64] (pre-scaled by 0.125*log2e), g_k [bh][s][64], g_vT [bh][64][s]
__device__ float g_q[BB * HH * SS * DHD];
__device__ float g_k[BB * HH * SS * DHD];
__device__ float g_vT[BB * HH * DHD * SS];

// ---------------- helpers ----------------
__device__ __forceinline__ unsigned long long pack_dup(float x) {
    unsigned long long r;
    asm("mov.b64 %0, {%1, %1};" : "=l"(r) : "f"(x));
    return r;
}
__device__ __forceinline__ void ffma2(unsigned long long& d,
                                      unsigned long long a,
                                      unsigned long long b) {
    asm("fma.rn.f32x2 %0, %1, %2, %0;" : "+l"(d) : "l"(a), "l"(b));
}
__device__ __forceinline__ float2 unpack2(unsigned long long v) {
    float2 f;
    asm("mov.b64 {%0, %1}, %2;" : "=f"(f.x), "=f"(f.y) : "l"(v));
    return f;
}
__device__ __forceinline__ float tf32rn(float x) {
    uint32_t u;
    asm("cvt.rn.tf32.f32 %0, %1;" : "=r"(u) : "f"(x));
    return __uint_as_float(u);
}
__device__ __forceinline__ float ex2f(float x) {
    float r;
    asm("ex2.approx.ftz.f32 %0, %1;" : "=f"(r) : "f"(x));
    return r;
}
__device__ __forceinline__ int sw_vec(int d, int g) {
    return d * 64 + (((g ^ (d >> 2)) & 15) << 2);
}
__device__ __forceinline__ uint32_t smem_to_u32(const void* p) {
    uint32_t a;
    asm("{ .reg .u64 t; cvta.to.shared.u64 t, %1; cvt.u32.u64 %0, t; }"
        : "=r"(a) : "l"(p));
    return a;
}
__device__ __forceinline__ void cp16(uint32_t dst, const void* src) {
    asm volatile("cp.async.cg.shared.global [%0], [%1], 16;"
                 :: "r"(dst), "l"(src) : "memory");
}
#define CP_COMMIT() asm volatile("cp.async.commit_group;" ::: "memory")
#define CP_WAIT_ALL() asm volatile("cp.async.wait_group 0;" ::: "memory")

#define MMA_TF32(c, a, b0, b1) \
    asm volatile("mma.sync.aligned.m16n8k8.row.col.f32.tf32.tf32.f32 " \
        "{%0,%1,%2,%3}, {%4,%5,%6,%7}, {%8,%9}, {%0,%1,%2,%3};" \
        : "+f"((c)[0]), "+f"((c)[1]), "+f"((c)[2]), "+f"((c)[3]) \
        : "r"((a)[0]), "r"((a)[1]), "r"((a)[2]), "r"((a)[3]), \
          "r"(b0), "r"(b1))

// octet-permute a row-chunk float4 using the lane^xorbit partner.
__device__ __forceinline__ float4 perm_shfl(float4 f, int xorbit, bool odd) {
    float4 p;
    p.x = __shfl_xor_sync(0xffffffffu, f.x, xorbit);
    p.y = __shfl_xor_sync(0xffffffffu, f.y, xorbit);
    p.z = __shfl_xor_sync(0xffffffffu, f.z, xorbit);
    p.w = __shfl_xor_sync(0xffffffffu, f.w, xorbit);
    return odd ? make_float4(p.z, f.z, p.w, f.w)
               : make_float4(f.x, p.x, f.y, p.y);
}

// =====================================================================
// Kernel 1: QKV projection (FFMA2 core), permuted tf32 outputs.
// q pre-scaled by 0.125*log2(e) so attention uses ex2 directly.
// =====================================================================
#define QSCALE 0.18033688011112042f   // 0.125 * log2(e)

__global__ __launch_bounds__(256) void qkv_kernel(
    const float* __restrict__ x,
    const float* __restrict__ Wq, const float* __restrict__ bq,
    const float* __restrict__ Wk, const float* __restrict__ bk,
    const float* __restrict__ Wv, const float* __restrict__ bv)
{
    extern __shared__ float sm1[];
    float* Xs  = sm1;
    float* Wqs = sm1 + 4096;
    float* Wks = sm1 + 8192;
    float* Wvs = sm1 + 12288;

    const int tile = blockIdx.x;      // 0..127
    const int h    = blockIdx.y;      // 0..15
    const int tid  = threadIdx.x;
    const int t0   = tile * 64;

#pragma unroll
    for (int k = 0; k < 4; k++) {
        int idx = tid + k * 256;
        int i   = idx >> 4;
        int d4  = (idx & 15) << 2;
        float4 v = *(const float4*)(x + (size_t)(t0 + i) * DD + h * DHD + d4);
        int g = (((i >> 2) ^ (d4 >> 2)) & 15) << 2;
        int o = g + (i & 3);
        Xs[(d4 + 0) * 64 + o] = v.x;
        Xs[(d4 + 1) * 64 + o] = v.y;
        Xs[(d4 + 2) * 64 + o] = v.z;
        Xs[(d4 + 3) * 64 + o] = v.w;
    }
#pragma unroll
    for (int k = 0; k < 4; k++) {
        int idx = tid + k * 256;
        int e   = idx >> 4;
        int d4  = (idx & 15) << 2;
        size_t base = ((size_t)h * DHD + e) * DHD + d4;
        int g = (((e >> 2) ^ (d4 >> 2)) & 15) << 2;
        int o = g + (e & 3);
        float4 a = *(const float4*)(Wq + base);
        Wqs[(d4 + 0) * 64 + o] = a.x; Wqs[(d4 + 1) * 64 + o] = a.y;
        Wqs[(d4 + 2) * 64 + o] = a.z; Wqs[(d4 + 3) * 64 + o] = a.w;
        float4 b = *(const float4*)(Wk + base);
        Wks[(d4 + 0) * 64 + o] = b.x; Wks[(d4 + 1) * 64 + o] = b.y;
        Wks[(d4 + 2) * 64 + o] = b.z; Wks[(d4 + 3) * 64 + o] = b.w;
        float4 c = *(const float4*)(Wv + base);
        Wvs[(d4 + 0) * 64 + o] = c.x; Wvs[(d4 + 1) * 64 + o] = c.y;
        Wvs[(d4 + 2) * 64 + o] = c.z; Wvs[(d4 + 3) * 64 + o] = c.w;
    }
    __syncthreads();

    const int ty = tid >> 4, tx = tid & 15;
    const int r0 = ty * 4, c0 = tx * 4;

    unsigned long long aq[4][2], ak[4][2], av_[4][2];
#pragma unroll
    for (int r = 0; r < 4; r++) {
        aq[r][0] = aq[r][1] = 0ull;
        ak[r][0] = ak[r][1] = 0ull;
        av_[r][0] = av_[r][1] = 0ull;
    }

#pragma unroll 8
    for (int d = 0; d < 64; d++) {
        float4 a4 = *(const float4*)&Xs[sw_vec(d, ty)];
        unsigned long long d0 = pack_dup(a4.x), d1 = pack_dup(a4.y),
                           d2 = pack_dup(a4.z), d3 = pack_dup(a4.w);
        ulonglong2 q2 = *(const ulonglong2*)&Wqs[sw_vec(d, tx)];
        ulonglong2 k2 = *(const ulonglong2*)&Wks[sw_vec(d, tx)];
        ulonglong2 v2 = *(const ulonglong2*)&Wvs[sw_vec(d, tx)];
        ffma2(aq[0][0], d0, q2.x); ffma2(aq[0][1], d0, q2.y);
        ffma2(aq[1][0], d1, q2.x); ffma2(aq[1][1], d1, q2.y);
        ffma2(aq[2][0], d2, q2.x); ffma2(aq[2][1], d2, q2.y);
        ffma2(aq[3][0], d3, q2.x); ffma2(aq[3][1], d3, q2.y);
        ffma2(ak[0][0], d0, k2.x); ffma2(ak[0][1], d0, k2.y);
        ffma2(ak[1][0], d1, k2.x); ffma2(ak[1][1], d1, k2.y);
        ffma2(ak[2][0], d2, k2.x); ffma2(ak[2][1], d2, k2.y);
        ffma2(ak[3][0], d3, k2.x); ffma2(ak[3][1], d3, k2.y);
        ffma2(av_[0][0], d0, v2.x); ffma2(av_[0][1], d0, v2.y);
        ffma2(av_[1][0], d1, v2.x); ffma2(av_[1][1], d1, v2.y);
        ffma2(av_[2][0], d2, v2.x); ffma2(av_[2][1], d2, v2.y);
        ffma2(av_[3][0], d3, v2.x); ffma2(av_[3][1], d3, v2.y);
    }

    float4 bq4 = *(const float4*)(bq + h * DHD + c0);
    float4 bk4 = *(const float4*)(bk + h * DHD + c0);
    float4 bv4 = *(const float4*)(bv + h * DHD + c0);

    const int bb = t0 >> 10;
    const int s0 = (t0 & 1023) + r0;
    const int bh = bb * HH + h;
    const bool oddx = (tx & 1);
    const bool oddy = (ty & 1);

    float vv[4][4];
#pragma unroll
    for (int r = 0; r < 4; r++) {
        size_t o = ((size_t)bh * SS + s0 + r) * DHD + c0;
        float2 u0, u1;
        u0 = unpack2(aq[r][0]); u1 = unpack2(aq[r][1]);
        float4 fq = make_float4(
            tf32rn((u0.x + bq4.x) * QSCALE), tf32rn((u0.y + bq4.y) * QSCALE),
            tf32rn((u1.x + bq4.z) * QSCALE), tf32rn((u1.y + bq4.w) * QSCALE));
        *(float4*)&g_q[o] = perm_shfl(fq, 1, oddx);
        u0 = unpack2(ak[r][0]); u1 = unpack2(ak[r][1]);
        float4 fk = make_float4(
            tf32rn(u0.x + bk4.x), tf32rn(u0.y + bk4.y),
            tf32rn(u1.x + bk4.z), tf32rn(u1.y + bk4.w));
        *(float4*)&g_k[o] = perm_shfl(fk, 1, oddx);
        u0 = unpack2(av_[r][0]); u1 = unpack2(av_[r][1]);
        vv[r][0] = tf32rn(u0.x + bv4.x); vv[r][1] = tf32rn(u0.y + bv4.y);
        vv[r][2] = tf32rn(u1.x + bv4.z); vv[r][3] = tf32rn(u1.y + bv4.w);
    }
#pragma unroll
    for (int j = 0; j < 4; j++) {
        float4 ft = make_float4(vv[0][j], vv[1][j], vv[2][j], vv[3][j]);
        size_t o = ((size_t)bh * DHD + c0 + j) * SS + s0;
        *(float4*)&g_vT[o] = perm_shfl(ft, 16, oddy);
    }
}

// =====================================================================
// Kernel 2: tf32 mma.sync flash attention, 128 threads (4 warps, 2m x 2n),
// 64 q-rows per CTA, KV tile 64. Separate P buffer; K single-buffered
// (K(kt+1) cp.async issued after the P-ready barrier, overlapping PV);
// V double-buffered. 2 barriers/kt. exp via ex2 (log2e folded upstream).
// SPW=72: LDS.64 frag loads pair-bank conflict-free. smem 74,240B,
// 3 CTAs/SM (regs<=170 via launch_bounds).
// =====================================================================
#define SPW 72
#define KF  0
#define V0F 4608          // 64*72
#define V1F 9216
#define PF  13824
#define LRF 18432         // 128 floats
#define ATTN_SMEM ((18432 + 128) * 4)   // 74240 B

__global__ void __launch_bounds__(128, 3) attn_kernel(float* __restrict__ out)
{
    extern __shared__ float smf[];
    const uint32_t smb = smem_to_u32(smf);
    const int tid  = threadIdx.x;
    const int wid  = tid >> 5;
    const int lane = tid & 31;
    const int g    = lane >> 2;
    const int c    = lane & 3;
    const int wm   = wid >> 1;      // 0..1 -> rows wm*32..
    const int wn   = wid & 1;       // 0..1 -> cols wn*32..

    const int qt = blockIdx.x;      // 0..15
    const int bh = blockIdx.y;      // 0..127
    const int b  = bh >> 4, h = bh & 15;
    const int m0 = qt * 64;

    const float* qbase = g_q + (size_t)bh * SS * DHD;
    const float* kbase = g_k + (size_t)bh * SS * DHD;
    const float* vTb   = g_vT + (size_t)bh * DHD * SS;

    float* Psm  = smf + PF;
    float* lred = smf + LRF;

    const int prow = tid >> 4;       // 0..7
    const int pch  = tid & 15;       // 16B chunk
    // precomputed cp.async bases (float-index *4 = bytes)
    const uint32_t kdst = smb + (KF  + prow * SPW + pch * 4) * 4;
    const uint32_t v0dst = smb + (V0F + prow * SPW + pch * 4) * 4;
    const uint32_t v1dst = smb + (V1F + prow * SPW + pch * 4) * 4;
    const float* kgs = kbase + (size_t)prow * DHD + pch * 4;
    const float* vgs = vTb + (size_t)prow * SS + pch * 4;

    // ---- prologue: async-load K(0)->K, V(0)->V0 ----
#pragma unroll
    for (int p = 0; p < 8; p++) {
        cp16(kdst + p * (8 * SPW * 4), kgs + (size_t)p * 8 * DHD);
        cp16(v0dst + p * (8 * SPW * 4), vgs + (size_t)p * 8 * SS);
    }
    CP_COMMIT();

    // ---- stage Q (permuted) into P buffer, stride SPW ----
#pragma unroll
    for (int it = 0; it < 8; it++) {
        int idx = tid + it * 128;
        int row = idx >> 4;
        int ch  = idx & 15;
        *(float4*)&Psm[row * SPW + ch * 4] =
            *(const float4*)(qbase + (size_t)(m0 + row) * DHD + ch * 4);
    }
    __syncthreads();

    uint32_t qa[2][8][4];
#pragma unroll
    for (int m = 0; m < 2; m++) {
        int r = wm * 32 + m * 16 + g;
#pragma unroll
        for (int s = 0; s < 8; s++) {
            float2 lo = *(const float2*)&Psm[r * SPW + s * 8 + 2 * c];
            float2 hi = *(const float2*)&Psm[(r + 8) * SPW + s * 8 + 2 * c];
            qa[m][s][0] = __float_as_uint(lo.x);
            qa[m][s][1] = __float_as_uint(hi.x);
            qa[m][s][2] = __float_as_uint(lo.y);
            qa[m][s][3] = __float_as_uint(hi.y);
        }
    }

    float oacc[2][4][4];
#pragma unroll
    for (int m = 0; m < 2; m++)
#pragma unroll
        for (int t = 0; t < 4; t++)
#pragma unroll
            for (int q = 0; q < 4; q++) oacc[m][t][q] = 0.f;
    float lacc[2][2] = {{0.f, 0.f}, {0.f, 0.f}};

    const int sl0 = ((c & 1) << 2) | (c >> 1);   // slot(2c); slot(2c+1)=sl0+2

    for (int kt = 0; kt < 16; kt++) {
        CP_WAIT_ALL();
        __syncthreads();  // K(kt),V(kt) visible; Q frags loaded (kt 0);
                          // prev-iter P/V reads done

        // prefetch V(kt+1) into the other V buffer (overlaps whole iter)
        if (kt < 15) {
            uint32_t vd = (kt & 1) ? v0dst : v1dst;
            const float* vsrc = vgs + (size_t)(kt + 1) * 64;
#pragma unroll
            for (int p = 0; p < 8; p++)
                cp16(vd + p * (8 * SPW * 4), vsrc + (size_t)p * 8 * SS);
            CP_COMMIT();
        }

        // ---- S = Q K^T ----
        const float* Kb = smf + KF;
        float sacc[2][4][4];
#pragma unroll
        for (int m = 0; m < 2; m++)
#pragma unroll
            for (int t = 0; t < 4; t++)
#pragma unroll
                for (int q = 0; q < 4; q++) sacc[m][t][q] = 0.f;
#pragma unroll
        for (int t = 0; t < 4; t++) {
            const float* bp = Kb + (wn * 32 + t * 8 + g) * SPW + 2 * c;
#pragma unroll
            for (int s = 0; s < 8; s++) {
                float2 b2 = *(const float2*)(bp + s * 8);
                uint32_t b0 = __float_as_uint(b2.x), b1 = __float_as_uint(b2.y);
                MMA_TF32(sacc[0][t], qa[0][s], b0, b1);
                MMA_TF32(sacc[1][t], qa[1][s], b0, b1);
            }
        }

        // ---- softmax (no max, base-2) + permuted P store ----
#pragma unroll
        for (int m = 0; m < 2; m++) {
            int r = wm * 32 + m * 16 + g;
            float* p0 = Psm + r * SPW + wn * 32;
            float* p1 = Psm + (r + 8) * SPW + wn * 32;
#pragma unroll
            for (int t = 0; t < 4; t++) {
                float e0 = tf32rn(ex2f(sacc[m][t][0]));
                float e1 = tf32rn(ex2f(sacc[m][t][1]));
                float e2 = tf32rn(ex2f(sacc[m][t][2]));
                float e3 = tf32rn(ex2f(sacc[m][t][3]));
                lacc[m][0] += e0 + e1;
                lacc[m][1] += e2 + e3;
                p0[t * 8 + sl0]     = e0;
                p0[t * 8 + sl0 + 2] = e1;
                p1[t * 8 + sl0]     = e2;
                p1[t * 8 + sl0 + 2] = e3;
            }
        }
        __syncthreads();  // P visible; all S-MMA K reads done

        // prefetch K(kt+1) into the (single) K buffer — overlaps PV
        if (kt < 15) {
            const float* ksrc = kgs + (size_t)(kt + 1) * 64 * DHD;
#pragma unroll
            for (int p = 0; p < 8; p++)
                cp16(kdst + p * (8 * SPW * 4), ksrc + (size_t)p * 8 * DHD);
            CP_COMMIT();
        }

        // ---- O += P V ----
        const float* Vb = smf + ((kt & 1) ? V1F : V0F);
#pragma unroll
        for (int s = 0; s < 8; s++) {
            uint32_t pa[2][4];
#pragma unroll
            for (int m = 0; m < 2; m++) {
                int r = wm * 32 + m * 16 + g;
                float2 a0 = *(const float2*)(Psm + r * SPW + s * 8 + 2 * c);
                float2 a1 = *(const float2*)(Psm + (r + 8) * SPW + s * 8 + 2 * c);
                pa[m][0] = __float_as_uint(a0.x);
                pa[m][1] = __float_as_uint(a1.x);
                pa[m][2] = __float_as_uint(a0.y);
                pa[m][3] = __float_as_uint(a1.y);
            }
#pragma unroll
            for (int t = 0; t < 4; t++) {
                float2 b2 = *(const float2*)(Vb + (wn * 32 + t * 8 + g) * SPW + s * 8 + 2 * c);
                uint32_t b0 = __float_as_uint(b2.x), b1 = __float_as_uint(b2.y);
                MMA_TF32(oacc[0][t], pa[0], b0, b1);
                MMA_TF32(oacc[1][t], pa[1], b0, b1);
            }
        }
    }

    // ---- epilogue: reduce l, normalize, store ----
#pragma unroll
    for (int m = 0; m < 2; m++)
#pragma unroll
        for (int hh = 0; hh < 2; hh++) {
            lacc[m][hh] += __shfl_xor_sync(0xffffffffu, lacc[m][hh], 1);
            lacc[m][hh] += __shfl_xor_sync(0xffffffffu, lacc[m][hh], 2);
        }
    if (c == 0) {
#pragma unroll
        for (int m = 0; m < 2; m++) {
            int r = wm * 32 + m * 16 + g;
            lred[r * 2 + wn]       = lacc[m][0];
            lred[(r + 8) * 2 + wn] = lacc[m][1];
        }
    }
    __syncthreads();

#pragma unroll
    for (int m = 0; m < 2; m++) {
        int r = wm * 32 + m * 16 + g;
        float inv0 = 1.f / (lred[r * 2] + lred[r * 2 + 1]);
        float inv1 = 1.f / (lred[(r + 8) * 2] + lred[(r + 8) * 2 + 1]);
        size_t o0 = (((size_t)b * SS + m0 + r) * HH + h) * DHD;
        size_t o1 = (((size_t)b * SS + m0 + r + 8) * HH + h) * DHD;
#pragma unroll
        for (int t = 0; t < 4; t++) {
            int col = wn * 32 + t * 8 + 2 * c;
            *(float2*)&out[o0 + col] =
                make_float2(oacc[m][t][0] * inv0, oacc[m][t][1] * inv0);
            *(float2*)&out[o1 + col] =
                make_float2(oacc[m][t][2] * inv1, oacc[m][t][3] * inv1);
        }
    }
}

// =====================================================================
extern "C" void kernel_launch(void* const* d_in, const int* in_sizes, int n_in,
                              void* d_out, int out_size)
{
    const float* x  = (const float*)d_in[0];
    const float* Wq = (const float*)d_in[1];
    const float* bq = (const float*)d_in[2];
    const float* Wk = (const float*)d_in[3];
    const float* bk = (const float*)d_in[4];
    const float* Wv = (const float*)d_in[5];
    const float* bv = (const float*)d_in[6];
    float* out = (float*)d_out;

    static bool attr_set = false;
    if (!attr_set) {
        cudaFuncSetAttribute(qkv_kernel,
                             cudaFuncAttributeMaxDynamicSharedMemorySize, 65536);
        cudaFuncSetAttribute(attn_kernel,
                             cudaFuncAttributeMaxDynamicSharedMemorySize, ATTN_SMEM);
        attr_set = true;
    }

    qkv_kernel<<<dim3(128, 16), 256, 65536>>>(x, Wq, bq, Wk, bk, Wv, bv);
    attn_kernel<<<dim3(16, 128), 128, ATTN_SMEM>>>(out);
}

// round 12
// speedup vs baseline: 1.4918x; 1.1334x over previous
#include <cuda_runtime.h>
#include <cstdint>

#define BB 8
#define SS 1024
#define DD 1024
#define HH 16
#define DHD 64   // head dim

// Scratch (tf32-rounded, octet-permuted cols: slot(w)=2*(w&3)+(w>>2) per 8-col octet):
// g_q [bh][s][64] (pre-scaled by 0.125*log2e), g_k [bh][s][64], g_vT [bh][64][s]
__device__ float g_q[BB * HH * SS * DHD];
__device__ float g_k[BB * HH * SS * DHD];
__device__ float g_vT[BB * HH * DHD * SS];

// ---------------- helpers ----------------
__device__ __forceinline__ float tf32rn(float x) {
    uint32_t u;
    asm("cvt.rn.tf32.f32 %0, %1;" : "=r"(u) : "f"(x));
    return __uint_as_float(u);
}
__device__ __forceinline__ float ex2f(float x) {
    float r;
    asm("ex2.approx.ftz.f32 %0, %1;" : "=f"(r) : "f"(x));
    return r;
}
__device__ __forceinline__ uint32_t smem_to_u32(const void* p) {
    uint32_t a;
    asm("{ .reg .u64 t; cvta.to.shared.u64 t, %1; cvt.u32.u64 %0, t; }"
        : "=r"(a) : "l"(p));
    return a;
}
__device__ __forceinline__ void cp16(uint32_t dst, const void* src) {
    asm volatile("cp.async.cg.shared.global [%0], [%1], 16;"
                 :: "r"(dst), "l"(src) : "memory");
}
#define CP_COMMIT() asm volatile("cp.async.commit_group;" ::: "memory")
#define CP_WAIT_ALL() asm volatile("cp.async.wait_group 0;" ::: "memory")

#define MMA_TF32(c, a, b0, b1) \
    asm volatile("mma.sync.aligned.m16n8k8.row.col.f32.tf32.tf32.f32 " \
        "{%0,%1,%2,%3}, {%4,%5,%6,%7}, {%8,%9}, {%0,%1,%2,%3};" \
        : "+f"((c)[0]), "+f"((c)[1]), "+f"((c)[2]), "+f"((c)[3]) \
        : "r"((a)[0]), "r"((a)[1]), "r"((a)[2]), "r"((a)[3]), \
          "r"(b0), "r"(b1))

// octet-permute a row-chunk float4 using the lane^xorbit partner.
__device__ __forceinline__ float4 perm_shfl(float4 f, int xorbit, bool odd) {
    float4 p;
    p.x = __shfl_xor_sync(0xffffffffu, f.x, xorbit);
    p.y = __shfl_xor_sync(0xffffffffu, f.y, xorbit);
    p.z = __shfl_xor_sync(0xffffffffu, f.z, xorbit);
    p.w = __shfl_xor_sync(0xffffffffu, f.w, xorbit);
    return odd ? make_float4(p.z, f.z, p.w, f.w)
               : make_float4(f.x, p.x, f.y, p.y);
}

#define QSCALE 0.18033688011112042f   // 0.125 * log2(e)

// =====================================================================
// Kernel 1: QKV projection on mma.sync tf32.
// grid (128 token-tiles of 64, 16 heads), 128 threads (4 warps 2m x 2n).
// X[64x64] (A frags, persistent) x {Wq,Wk,Wv}[e][d] (B, naturally [n][k]).
// k-octet permute applied at smem load on BOTH operands (cancels in dot).
// Dedicated OUT staging buffer; phases: stage -> bar -> STG (+ next GEMM
// overlapping the STG) -> bar -> next stage. No input-buffer reuse.
// FIX vs R10/R11: vT store uses s0 (token within batch), not t0 (global
// flattened token) — t0 double-counted the batch already encoded in bh,
// writing out of bounds for tiles >= 16.
// =====================================================================
#define QSPW 72
#define XSo  0
#define WQo  4608         // 64*72
#define WKo  9216
#define WVo  13824
#define OUTo 18432
#define QKV_SMEM ((18432 + 4608) * 4)   // 92160 B

#define QKV_GEMM(acc, Woff) do { \
    _Pragma("unroll") \
    for (int m_ = 0; m_ < 2; m_++) \
        _Pragma("unroll") \
        for (int t_ = 0; t_ < 4; t_++) \
            _Pragma("unroll") \
            for (int q_ = 0; q_ < 4; q_++) (acc)[m_][t_][q_] = 0.f; \
    _Pragma("unroll") \
    for (int t_ = 0; t_ < 4; t_++) { \
        const float* bp_ = smf + (Woff) + (wn * 32 + t_ * 8 + g) * QSPW + 2 * c; \
        _Pragma("unroll") \
        for (int s_ = 0; s_ < 8; s_++) { \
            float2 b2_ = *(const float2*)(bp_ + s_ * 8); \
            uint32_t b0_ = __float_as_uint(b2_.x), b1_ = __float_as_uint(b2_.y); \
            MMA_TF32((acc)[0][t_], qa[0][s_], b0_, b1_); \
            MMA_TF32((acc)[1][t_], qa[1][s_], b0_, b1_); \
        } \
    } \
} while (0)

__global__ void __launch_bounds__(128) qkv_kernel(
    const float* __restrict__ x,
    const float* __restrict__ Wq, const float* __restrict__ bq,
    const float* __restrict__ Wk, const float* __restrict__ bk,
    const float* __restrict__ Wv, const float* __restrict__ bv)
{
    extern __shared__ float smf[];
    const int tid  = threadIdx.x;
    const int wid  = tid >> 5;
    const int lane = tid & 31;
    const int g    = lane >> 2;
    const int c    = lane & 3;
    const int wm   = wid >> 1;
    const int wn   = wid & 1;

    const int tile = blockIdx.x;     // 0..127
    const int h    = blockIdx.y;     // 0..15
    const int t0   = tile * 64;
    const int prow = tid >> 4;       // 0..7
    const int pch  = tid & 15;       // float4 chunk
    const bool odd = pch & 1;

    // ---- load X and W tiles, octet-permuted along k ----
#pragma unroll
    for (int p = 0; p < 8; p++) {
        int row = prow + p * 8;
        float4 xv = *(const float4*)(x + (size_t)(t0 + row) * DD + h * DHD + pch * 4);
        *(float4*)&smf[XSo + row * QSPW + pch * 4] = perm_shfl(xv, 1, odd);
        size_t wb = ((size_t)h * DHD + row) * DHD + pch * 4;
        *(float4*)&smf[WQo + row * QSPW + pch * 4] =
            perm_shfl(*(const float4*)(Wq + wb), 1, odd);
        *(float4*)&smf[WKo + row * QSPW + pch * 4] =
            perm_shfl(*(const float4*)(Wk + wb), 1, odd);
        *(float4*)&smf[WVo + row * QSPW + pch * 4] =
            perm_shfl(*(const float4*)(Wv + wb), 1, odd);
    }
    __syncthreads();   // B1

    // ---- A fragments from X (persistent for all 3 GEMMs) ----
    uint32_t qa[2][8][4];
#pragma unroll
    for (int m = 0; m < 2; m++) {
        int r = wm * 32 + m * 16 + g;
#pragma unroll
        for (int s = 0; s < 8; s++) {
            float2 lo = *(const float2*)&smf[XSo + r * QSPW + s * 8 + 2 * c];
            float2 hi = *(const float2*)&smf[XSo + (r + 8) * QSPW + s * 8 + 2 * c];
            qa[m][s][0] = __float_as_uint(lo.x);
            qa[m][s][1] = __float_as_uint(hi.x);
            qa[m][s][2] = __float_as_uint(lo.y);
            qa[m][s][3] = __float_as_uint(hi.y);
        }
    }

    const int sl0 = ((c & 1) << 2) | (c >> 1);       // slot(2c); slot(2c+1)=sl0+2
    const int slg = 2 * (g & 3) + (g >> 2);          // slot(g)
    const int bh  = (t0 >> 10) * HH + h;
    const int s0  = (t0 & 1023);

    // ---- GEMM q ----
    float acc[2][4][4];
    QKV_GEMM(acc, WQo);

    // stage q (bias, scale, tf32, permuted cols) into OUT
    {
        float b0r[4], b1r[4];
#pragma unroll
        for (int t = 0; t < 4; t++) {
            int e = wn * 32 + t * 8 + 2 * c;
            b0r[t] = bq[h * DHD + e];
            b1r[t] = bq[h * DHD + e + 1];
        }
#pragma unroll
        for (int m = 0; m < 2; m++) {
            int r = wm * 32 + m * 16 + g;
            float* p0 = &smf[OUTo + r * QSPW + wn * 32];
            float* p1 = &smf[OUTo + (r + 8) * QSPW + wn * 32];
#pragma unroll
            for (int t = 0; t < 4; t++) {
                p0[t * 8 + sl0]     = tf32rn((acc[m][t][0] + b0r[t]) * QSCALE);
                p0[t * 8 + sl0 + 2] = tf32rn((acc[m][t][1] + b1r[t]) * QSCALE);
                p1[t * 8 + sl0]     = tf32rn((acc[m][t][2] + b0r[t]) * QSCALE);
                p1[t * 8 + sl0 + 2] = tf32rn((acc[m][t][3] + b1r[t]) * QSCALE);
            }
        }
    }
    __syncthreads();   // B2: q fully staged

    // STG q (coalesced) + GEMM k overlapping
#pragma unroll
    for (int p = 0; p < 8; p++) {
        int row = prow + p * 8;
        *(float4*)&g_q[((size_t)bh * SS + s0 + row) * DHD + pch * 4] =
            *(const float4*)&smf[OUTo + row * QSPW + pch * 4];
    }
    float acck[2][4][4];
    QKV_GEMM(acck, WKo);
    __syncthreads();   // B3: all STG-q reads of OUT done

    // stage k into OUT
    {
        float b0r[4], b1r[4];
#pragma unroll
        for (int t = 0; t < 4; t++) {
            int e = wn * 32 + t * 8 + 2 * c;
            b0r[t] = bk[h * DHD + e];
            b1r[t] = bk[h * DHD + e + 1];
        }
#pragma unroll
        for (int m = 0; m < 2; m++) {
            int r = wm * 32 + m * 16 + g;
            float* p0 = &smf[OUTo + r * QSPW + wn * 32];
            float* p1 = &smf[OUTo + (r + 8) * QSPW + wn * 32];
#pragma unroll
            for (int t = 0; t < 4; t++) {
                p0[t * 8 + sl0]     = tf32rn(acck[m][t][0] + b0r[t]);
                p0[t * 8 + sl0 + 2] = tf32rn(acck[m][t][1] + b1r[t]);
                p1[t * 8 + sl0]     = tf32rn(acck[m][t][2] + b0r[t]);
                p1[t * 8 + sl0 + 2] = tf32rn(acck[m][t][3] + b1r[t]);
            }
        }
    }
    __syncthreads();   // B4: k fully staged

    // STG k + GEMM v overlapping
#pragma unroll
    for (int p = 0; p < 8; p++) {
        int row = prow + p * 8;
        *(float4*)&g_k[((size_t)bh * SS + s0 + row) * DHD + pch * 4] =
            *(const float4*)&smf[OUTo + row * QSPW + pch * 4];
    }
    float accv[2][4][4];
    QKV_GEMM(accv, WVo);
    __syncthreads();   // B5: all STG-k reads of OUT done

    // stage v TRANSPOSED into OUT: [e][token], tokens octet-permuted
    {
        float b0r[4], b1r[4];
#pragma unroll
        for (int t = 0; t < 4; t++) {
            int e = wn * 32 + t * 8 + 2 * c;
            b0r[t] = bv[h * DHD + e];
            b1r[t] = bv[h * DHD + e + 1];
        }
#pragma unroll
        for (int m = 0; m < 2; m++) {
            int r    = wm * 32 + m * 16 + g;
            int ptk0 = r - g + slg;        // permuted token slot (row r)
            int ptk1 = ptk0 + 8;           // row r+8 (next octet, same slot)
#pragma unroll
            for (int t = 0; t < 4; t++) {
                int e = wn * 32 + t * 8 + 2 * c;
                smf[OUTo + e * QSPW + ptk0]       = tf32rn(accv[m][t][0] + b0r[t]);
                smf[OUTo + (e + 1) * QSPW + ptk0] = tf32rn(accv[m][t][1] + b1r[t]);
                smf[OUTo + e * QSPW + ptk1]       = tf32rn(accv[m][t][2] + b0r[t]);
                smf[OUTo + (e + 1) * QSPW + ptk1] = tf32rn(accv[m][t][3] + b1r[t]);
            }
        }
    }
    __syncthreads();   // B6: v staged

    // STG vT: rows are e, columns are (permuted) tokens WITHIN the batch (s0!)
#pragma unroll
    for (int p = 0; p < 8; p++) {
        int erow = prow + p * 8;
        *(float4*)&g_vT[((size_t)bh * DHD + erow) * SS + s0 + pch * 4] =
            *(const float4*)&smf[OUTo + erow * QSPW + pch * 4];
    }
}

// =====================================================================
// Kernel 2: tf32 mma.sync flash attention (byte-identical to R9 pass).
// =====================================================================
#define SPW 72
#define KF  0
#define V0F 4608
#define V1F 9216
#define PF  13824
#define LRF 18432
#define ATTN_SMEM ((18432 + 128) * 4)   // 74240 B

__global__ void __launch_bounds__(128, 3) attn_kernel(float* __restrict__ out)
{
    extern __shared__ float smf[];
    const uint32_t smb = smem_to_u32(smf);
    const int tid  = threadIdx.x;
    const int wid  = tid >> 5;
    const int lane = tid & 31;
    const int g    = lane >> 2;
    const int c    = lane & 3;
    const int wm   = wid >> 1;
    const int wn   = wid & 1;

    const int qt = blockIdx.x;
    const int bh = blockIdx.y;
    const int b  = bh >> 4, h = bh & 15;
    const int m0 = qt * 64;

    const float* qbase = g_q + (size_t)bh * SS * DHD;
    const float* kbase = g_k + (size_t)bh * SS * DHD;
    const float* vTb   = g_vT + (size_t)bh * DHD * SS;

    float* Psm  = smf + PF;
    float* lred = smf + LRF;

    const int prow = tid >> 4;
    const int pch  = tid & 15;
    const uint32_t kdst  = smb + (KF  + prow * SPW + pch * 4) * 4;
    const uint32_t v0dst = smb + (V0F + prow * SPW + pch * 4) * 4;
    const uint32_t v1dst = smb + (V1F + prow * SPW + pch * 4) * 4;
    const float* kgs = kbase + (size_t)prow * DHD + pch * 4;
    const float* vgs = vTb + (size_t)prow * SS + pch * 4;

#pragma unroll
    for (int p = 0; p < 8; p++) {
        cp16(kdst + p * (8 * SPW * 4), kgs + (size_t)p * 8 * DHD);
        cp16(v0dst + p * (8 * SPW * 4), vgs + (size_t)p * 8 * SS);
    }
    CP_COMMIT();

#pragma unroll
    for (int it = 0; it < 8; it++) {
        int idx = tid + it * 128;
        int row = idx >> 4;
        int ch  = idx & 15;
        *(float4*)&Psm[row * SPW + ch * 4] =
            *(const float4*)(qbase + (size_t)(m0 + row) * DHD + ch * 4);
    }
    __syncthreads();

    uint32_t qa[2][8][4];
#pragma unroll
    for (int m = 0; m < 2; m++) {
        int r = wm * 32 + m * 16 + g;
#pragma unroll
        for (int s = 0; s < 8; s++) {
            float2 lo = *(const float2*)&Psm[r * SPW + s * 8 + 2 * c];
            float2 hi = *(const float2*)&Psm[(r + 8) * SPW + s * 8 + 2 * c];
            qa[m][s][0] = __float_as_uint(lo.x);
            qa[m][s][1] = __float_as_uint(hi.x);
            qa[m][s][2] = __float_as_uint(lo.y);
            qa[m][s][3] = __float_as_uint(hi.y);
        }
    }

    float oacc[2][4][4];
#pragma unroll
    for (int m = 0; m < 2; m++)
#pragma unroll
        for (int t = 0; t < 4; t++)
#pragma unroll
            for (int q = 0; q < 4; q++) oacc[m][t][q] = 0.f;
    float lacc[2][2] = {{0.f, 0.f}, {0.f, 0.f}};

    const int sl0 = ((c & 1) << 2) | (c >> 1);

    for (int kt = 0; kt < 16; kt++) {
        CP_WAIT_ALL();
        __syncthreads();

        if (kt < 15) {
            uint32_t vd = (kt & 1) ? v0dst : v1dst;
            const float* vsrc = vgs + (size_t)(kt + 1) * 64;
#pragma unroll
            for (int p = 0; p < 8; p++)
                cp16(vd + p * (8 * SPW * 4), vsrc + (size_t)p * 8 * SS);
            CP_COMMIT();
        }

        const float* Kb = smf + KF;
        float sacc[2][4][4];
#pragma unroll
        for (int m = 0; m < 2; m++)
#pragma unroll
            for (int t = 0; t < 4; t++)
#pragma unroll
                for (int q = 0; q < 4; q++) sacc[m][t][q] = 0.f;
#pragma unroll
        for (int t = 0; t < 4; t++) {
            const float* bp = Kb + (wn * 32 + t * 8 + g) * SPW + 2 * c;
#pragma unroll
            for (int s = 0; s < 8; s++) {
                float2 b2 = *(const float2*)(bp + s * 8);
                uint32_t b0 = __float_as_uint(b2.x), b1 = __float_as_uint(b2.y);
                MMA_TF32(sacc[0][t], qa[0][s], b0, b1);
                MMA_TF32(sacc[1][t], qa[1][s], b0, b1);
            }
        }

#pragma unroll
        for (int m = 0; m < 2; m++) {
            int r = wm * 32 + m * 16 + g;
            float* p0 = Psm + r * SPW + wn * 32;
            float* p1 = Psm + (r + 8) * SPW + wn * 32;
#pragma unroll
            for (int t = 0; t < 4; t++) {
                float e0 = tf32rn(ex2f(sacc[m][t][0]));
                float e1 = tf32rn(ex2f(sacc[m][t][1]));
                float e2 = tf32rn(ex2f(sacc[m][t][2]));
                float e3 = tf32rn(ex2f(sacc[m][t][3]));
                lacc[m][0] += e0 + e1;
                lacc[m][1] += e2 + e3;
                p0[t * 8 + sl0]     = e0;
                p0[t * 8 + sl0 + 2] = e1;
                p1[t * 8 + sl0]     = e2;
                p1[t * 8 + sl0 + 2] = e3;
            }
        }
        __syncthreads();

        if (kt < 15) {
            const float* ksrc = kgs + (size_t)(kt + 1) * 64 * DHD;
#pragma unroll
            for (int p = 0; p < 8; p++)
                cp16(kdst + p * (8 * SPW * 4), ksrc + (size_t)p * 8 * DHD);
            CP_COMMIT();
        }

        const float* Vb = smf + ((kt & 1) ? V1F : V0F);
#pragma unroll
        for (int s = 0; s < 8; s++) {
            uint32_t pa[2][4];
#pragma unroll
            for (int m = 0; m < 2; m++) {
                int r = wm * 32 + m * 16 + g;
                float2 a0 = *(const float2*)(Psm + r * SPW + s * 8 + 2 * c);
                float2 a1 = *(const float2*)(Psm + (r + 8) * SPW + s * 8 + 2 * c);
                pa[m][0] = __float_as_uint(a0.x);
                pa[m][1] = __float_as_uint(a1.x);
                pa[m][2] = __float_as_uint(a0.y);
                pa[m][3] = __float_as_uint(a1.y);
            }
#pragma unroll
            for (int t = 0; t < 4; t++) {
                float2 b2 = *(const float2*)(Vb + (wn * 32 + t * 8 + g) * SPW + s * 8 + 2 * c);
                uint32_t b0 = __float_as_uint(b2.x), b1 = __float_as_uint(b2.y);
                MMA_TF32(oacc[0][t], pa[0], b0, b1);
                MMA_TF32(oacc[1][t], pa[1], b0, b1);
            }
        }
    }

#pragma unroll
    for (int m = 0; m < 2; m++)
#pragma unroll
        for (int hh = 0; hh < 2; hh++) {
            lacc[m][hh] += __shfl_xor_sync(0xffffffffu, lacc[m][hh], 1);
            lacc[m][hh] += __shfl_xor_sync(0xffffffffu, lacc[m][hh], 2);
        }
    if (c == 0) {
#pragma unroll
        for (int m = 0; m < 2; m++) {
            int r = wm * 32 + m * 16 + g;
            lred[r * 2 + wn]       = lacc[m][0];
            lred[(r + 8) * 2 + wn] = lacc[m][1];
        }
    }
    __syncthreads();

#pragma unroll
    for (int m = 0; m < 2; m++) {
        int r = wm * 32 + m * 16 + g;
        float inv0 = 1.f / (lred[r * 2] + lred[r * 2 + 1]);
        float inv1 = 1.f / (lred[(r + 8) * 2] + lred[(r + 8) * 2 + 1]);
        size_t o0 = (((size_t)b * SS + m0 + r) * HH + h) * DHD;
        size_t o1 = (((size_t)b * SS + m0 + r + 8) * HH + h) * DHD;
#pragma unroll
        for (int t = 0; t < 4; t++) {
            int col = wn * 32 + t * 8 + 2 * c;
            *(float2*)&out[o0 + col] =
                make_float2(oacc[m][t][0] * inv0, oacc[m][t][1] * inv0);
            *(float2*)&out[o1 + col] =
                make_float2(oacc[m][t][2] * inv1, oacc[m][t][3] * inv1);
        }
    }
}

// =====================================================================
extern "C" void kernel_launch(void* const* d_in, const int* in_sizes, int n_in,
                              void* d_out, int out_size)
{
    const float* x  = (const float*)d_in[0];
    const float* Wq = (const float*)d_in[1];
    const float* bq = (const float*)d_in[2];
    const float* Wk = (const float*)d_in[3];
    const float* bk = (const float*)d_in[4];
    const float* Wv = (const float*)d_in[5];
    const float* bv = (const float*)d_in[6];
    float* out = (float*)d_out;

    static bool attr_set = false;
    if (!attr_set) {
        cudaFuncSetAttribute(qkv_kernel,
                             cudaFuncAttributeMaxDynamicSharedMemorySize, QKV_SMEM);
        cudaFuncSetAttribute(attn_kernel,
                             cudaFuncAttributeMaxDynamicSharedMemorySize, ATTN_SMEM);
        attr_set = true;
    }

    qkv_kernel<<<dim3(128, 16), 128, QKV_SMEM>>>(x, Wq, bq, Wk, bk, Wv, bv);
    attn_kernel<<<dim3(16, 128), 128, ATTN_SMEM>>>(out);
}